// round 16
// baseline (speedup 1.0000x reference)
#include <cuda_runtime.h>
#include <math.h>

// B=2 N=512 CS=384 CZ=128 H=12 D=16 P=4 PV=8
// PROJ cols: q 0..191 | k 192..383 | v 384..575 | qp 576..719 | kp 720..863 | vp 864..1151
// CAT=2112: o_hat 0..1535 | o 1536..1727 | o_hp 1728..2015 | norm 2016..2111

__device__ float WPROJ[384 * 1152];
__device__ float PROJ[1024 * 1152];
__device__ float QQb[1024 * 384];
__device__ float KKb[1024 * 384];
__device__ float VTb[1024 * 480];           // per key row: 12h x [v(16) | tv(24)]
__device__ float CATb[1024 * 2112];
__device__ float SCA[2 * 12 * 512 * 512];   // scores, then unnormalized exp weights (in-place)
__device__ float SMAXPART[24 * 512 * 8];    // per (b,h,i): block maxes over 4 j-blocks (slots 0..3)
__device__ float RINVb[24 * 512];           // per (b,h,i): 1/sum(exp)
__device__ float OHP[1024 * 288];           // global-frame point aggregation
__device__ float OUTPART[4 * 1024 * 384];   // split-K partials for output GEMM

// ---------------- K1: pack projection weights ----------------
__global__ void kpack(const float* __restrict__ wq, const float* __restrict__ wk,
                      const float* __restrict__ wv, const float* __restrict__ wqp,
                      const float* __restrict__ wkp, const float* __restrict__ wvp) {
    int e = blockIdx.x * 256 + threadIdx.x;  // 1728*256 = 442368 = 384*1152
    int c = e / 1152, col = e - c * 1152;
    float v;
    if (col < 192)       v = wq[c * 192 + col];
    else if (col < 384)  v = wk[c * 192 + col - 192];
    else if (col < 576)  v = wv[c * 192 + col - 384];
    else if (col < 720)  v = wqp[c * 144 + col - 576];
    else if (col < 864)  v = wkp[c * 144 + col - 720];
    else                 v = wvp[c * 288 + col - 864];
    WPROJ[e] = v;
}

// ---------------- tiled SGEMM 64x64x16, double-buffered, optional split-K ----------------
__global__ __launch_bounds__(256)
void sgemm_k(const float* __restrict__ A, const float* __restrict__ Bm,
             float* __restrict__ C, int M, int Nn, int K, int Ksl,
             const float* __restrict__ bias) {
    __shared__ float As[2][16][64];
    __shared__ float Bs[2][16][64];
    int t = threadIdx.x;
    int tx = t % 16, ty = t / 16;
    int row0 = blockIdx.y * 64, col0 = blockIdx.x * 64;
    int kbeg = blockIdx.z * Ksl;
    float* Cp = C + (size_t)blockIdx.z * M * Nn;
    int ar = t >> 2, akk = (t & 3) * 4;     // A stage: row, k4
    int bkk = t >> 4, bn4 = (t & 15) * 4;   // B stage: k, n4
    float acc[4][4] = {};
    {   // preload stage 0
        float4 va = *(const float4*)(A + (size_t)(row0 + ar) * K + kbeg + akk);
        As[0][akk][ar] = va.x; As[0][akk + 1][ar] = va.y;
        As[0][akk + 2][ar] = va.z; As[0][akk + 3][ar] = va.w;
        *(float4*)(&Bs[0][bkk][bn4]) =
            *(const float4*)(Bm + (size_t)(kbeg + bkk) * Nn + col0 + bn4);
    }
    __syncthreads();
    int nst = Ksl / 16;
    for (int s = 0; s < nst; s++) {
        int cur = s & 1, nxt = cur ^ 1;
        float4 va, vb;
        bool more = (s + 1 < nst);
        if (more) {   // issue next-tile LDGs before compute (latency hidden)
            int k0 = kbeg + (s + 1) * 16;
            va = *(const float4*)(A + (size_t)(row0 + ar) * K + k0 + akk);
            vb = *(const float4*)(Bm + (size_t)(k0 + bkk) * Nn + col0 + bn4);
        }
#pragma unroll
        for (int kk = 0; kk < 16; kk++) {
            float4 ra = *(const float4*)(&As[cur][kk][ty * 4]);
            float4 rb = *(const float4*)(&Bs[cur][kk][tx * 4]);
            acc[0][0] += ra.x * rb.x; acc[0][1] += ra.x * rb.y; acc[0][2] += ra.x * rb.z; acc[0][3] += ra.x * rb.w;
            acc[1][0] += ra.y * rb.x; acc[1][1] += ra.y * rb.y; acc[1][2] += ra.y * rb.z; acc[1][3] += ra.y * rb.w;
            acc[2][0] += ra.z * rb.x; acc[2][1] += ra.z * rb.y; acc[2][2] += ra.z * rb.z; acc[2][3] += ra.z * rb.w;
            acc[3][0] += ra.w * rb.x; acc[3][1] += ra.w * rb.y; acc[3][2] += ra.w * rb.z; acc[3][3] += ra.w * rb.w;
        }
        if (more) {
            As[nxt][akk][ar] = va.x; As[nxt][akk + 1][ar] = va.y;
            As[nxt][akk + 2][ar] = va.z; As[nxt][akk + 3][ar] = va.w;
            *(float4*)(&Bs[nxt][bkk][bn4]) = vb;
            __syncthreads();
        }
    }
#pragma unroll
    for (int u = 0; u < 4; u++) {
        int r = row0 + ty * 4 + u;
        float4 o = make_float4(acc[u][0], acc[u][1], acc[u][2], acc[u][3]);
        if (bias) {
            const float4 bb = *(const float4*)(bias + col0 + tx * 4);
            o.x += bb.x; o.y += bb.y; o.z += bb.z; o.w += bb.w;
        }
        *(float4*)(Cp + (size_t)r * Nn + col0 + tx * 4) = o;
    }
}

// ---------------- reduce split-K partials + bias (float4) ----------------
__global__ void kreduce(float* __restrict__ out, const float* __restrict__ bout) {
    int e = (blockIdx.x * 256 + threadIdx.x) * 4;   // 98304 threads x 4 = 393216
    const int PL = 1024 * 384;
    float4 a = *(const float4*)(OUTPART + e);
    float4 b = *(const float4*)(OUTPART + PL + e);
    float4 c = *(const float4*)(OUTPART + 2 * PL + e);
    float4 d = *(const float4*)(OUTPART + 3 * PL + e);
    float4 bb = *(const float4*)(bout + (e % 384));
    float4 o;
    o.x = a.x + b.x + c.x + d.x + bb.x;
    o.y = a.y + b.y + c.y + d.y + bb.y;
    o.z = a.z + b.z + c.z + d.z + bb.z;
    o.w = a.w + b.w + c.w + d.w + bb.w;
    *(float4*)(out + e) = o;
}

// ---------------- K3: rigid transforms + QQ/KK/VT packing ----------------
__global__ void ktransform(const float* __restrict__ rots, const float* __restrict__ trans,
                           const float* __restrict__ gamma) {
    int row = blockIdx.x;
    int h = threadIdx.x;
    if (h >= 12) return;
    const float* pr = PROJ + (size_t)row * 1152;
    float R0 = rots[row * 9 + 0], R1 = rots[row * 9 + 1], R2 = rots[row * 9 + 2];
    float R3 = rots[row * 9 + 3], R4 = rots[row * 9 + 4], R5 = rots[row * 9 + 5];
    float R6 = rots[row * 9 + 6], R7 = rots[row * 9 + 7], R8 = rots[row * 9 + 8];
    float t0 = trans[row * 3 + 0], t1 = trans[row * 3 + 1], t2 = trans[row * 3 + 2];
    float* QQ = QQb + (size_t)row * 384 + h * 32;
    float* KK = KKb + (size_t)row * 384 + h * 32;
    float cg = 0.11785113019775793f * gamma[h];  // 0.5 * sqrt(2/36) * gamma
#pragma unroll
    for (int d = 0; d < 16; d++) {
        QQ[d] = pr[h * 16 + d] * 0.25f;          // fold 1/sqrt(D)
        KK[d] = pr[192 + h * 16 + d];
    }
    float sq2 = 0.f, sk2 = 0.f;
#pragma unroll
    for (int p = 0; p < 4; p++) {
        const float* qp = pr + 576 + h * 12 + p * 3;
        float x = qp[0], y = qp[1], zz = qp[2];
        float gx = R0 * x + R1 * y + R2 * zz + t0;
        float gy = R3 * x + R4 * y + R5 * zz + t1;
        float gz = R6 * x + R7 * y + R8 * zz + t2;
        QQ[16 + p * 3 + 0] = 2.f * cg * gx;
        QQ[16 + p * 3 + 1] = 2.f * cg * gy;
        QQ[16 + p * 3 + 2] = 2.f * cg * gz;
        sq2 += gx * gx + gy * gy + gz * gz;
        const float* kp = pr + 720 + h * 12 + p * 3;
        x = kp[0]; y = kp[1]; zz = kp[2];
        gx = R0 * x + R1 * y + R2 * zz + t0;
        gy = R3 * x + R4 * y + R5 * zz + t1;
        gz = R6 * x + R7 * y + R8 * zz + t2;
        KK[16 + p * 3 + 0] = gx; KK[16 + p * 3 + 1] = gy; KK[16 + p * 3 + 2] = gz;
        sk2 += gx * gx + gy * gy + gz * gz;
    }
    QQ[28] = -cg;       KK[28] = sk2;
    QQ[29] = -cg * sq2; KK[29] = 1.f;
    QQ[30] = 0.f; QQ[31] = 0.f; KK[30] = 0.f; KK[31] = 0.f;
    // pack [v | tv] for kagg
    float* vt = VTb + (size_t)row * 480 + h * 40;
#pragma unroll
    for (int d = 0; d < 16; d++) vt[d] = pr[384 + h * 16 + d];
#pragma unroll
    for (int p = 0; p < 8; p++) {
        const float* vp = pr + 864 + h * 24 + p * 3;
        float x = vp[0], y = vp[1], zz = vp[2];
        vt[16 + p * 3 + 0] = R0 * x + R1 * y + R2 * zz + t0;
        vt[16 + p * 3 + 1] = R3 * x + R4 * y + R5 * zz + t1;
        vt[16 + p * 3 + 2] = R6 * x + R7 * y + R8 * zz + t2;
    }
}

// ---------------- K4: score GEMM 64i x 128j + per-row block maxes ----------------
__global__ __launch_bounds__(256) void kscore() {
    __shared__ float As[32][68];    // QQ: [c][i], 64 i
    __shared__ float Bs[32][132];   // KK: [c][j], 128 j
    int t = threadIdx.x;
    int bh = blockIdx.z, b = bh / 12, h = bh % 12;
    int i0 = blockIdx.y * 64, j0 = blockIdx.x * 128;
#pragma unroll
    for (int s = 0; s < 2; s++) {
        int idx = t + s * 256;
        int r = idx >> 3, c4 = (idx & 7) * 4;
        float4 va = *(const float4*)(QQb + (size_t)(b * 512 + i0 + r) * 384 + h * 32 + c4);
        As[c4][r] = va.x; As[c4 + 1][r] = va.y; As[c4 + 2][r] = va.z; As[c4 + 3][r] = va.w;
    }
#pragma unroll
    for (int s = 0; s < 4; s++) {
        int idx = t + s * 256;
        int r = idx >> 3, c4 = (idx & 7) * 4;
        float4 vb = *(const float4*)(KKb + (size_t)(b * 512 + j0 + r) * 384 + h * 32 + c4);
        Bs[c4][r] = vb.x; Bs[c4 + 1][r] = vb.y; Bs[c4 + 2][r] = vb.z; Bs[c4 + 3][r] = vb.w;
    }
    __syncthreads();
    int tx = t & 31, ty = t >> 5;   // tx: 32 x 4j = 128, ty: 8 x 8i = 64
    float acc[8][4] = {};
#pragma unroll
    for (int kk = 0; kk < 32; kk++) {
        float4 a0 = *(const float4*)(&As[kk][ty * 8]);
        float4 a1 = *(const float4*)(&As[kk][ty * 8 + 4]);
        float4 rb = *(const float4*)(&Bs[kk][tx * 4]);
        acc[0][0] += a0.x * rb.x; acc[0][1] += a0.x * rb.y; acc[0][2] += a0.x * rb.z; acc[0][3] += a0.x * rb.w;
        acc[1][0] += a0.y * rb.x; acc[1][1] += a0.y * rb.y; acc[1][2] += a0.y * rb.z; acc[1][3] += a0.y * rb.w;
        acc[2][0] += a0.z * rb.x; acc[2][1] += a0.z * rb.y; acc[2][2] += a0.z * rb.z; acc[2][3] += a0.z * rb.w;
        acc[3][0] += a0.w * rb.x; acc[3][1] += a0.w * rb.y; acc[3][2] += a0.w * rb.z; acc[3][3] += a0.w * rb.w;
        acc[4][0] += a1.x * rb.x; acc[4][1] += a1.x * rb.y; acc[4][2] += a1.x * rb.z; acc[4][3] += a1.x * rb.w;
        acc[5][0] += a1.y * rb.x; acc[5][1] += a1.y * rb.y; acc[5][2] += a1.y * rb.z; acc[5][3] += a1.y * rb.w;
        acc[6][0] += a1.z * rb.x; acc[6][1] += a1.z * rb.y; acc[6][2] += a1.z * rb.z; acc[6][3] += a1.z * rb.w;
        acc[7][0] += a1.w * rb.x; acc[7][1] += a1.w * rb.y; acc[7][2] += a1.w * rb.z; acc[7][3] += a1.w * rb.w;
    }
#pragma unroll
    for (int u = 0; u < 8; u++) {
        int rowi = i0 + ty * 8 + u;
        float4 o = make_float4(acc[u][0], acc[u][1], acc[u][2], acc[u][3]);
        *(float4*)(SCA + ((size_t)bh * 512 + rowi) * 512 + j0 + tx * 4) = o;
        float rm = fmaxf(fmaxf(acc[u][0], acc[u][1]), fmaxf(acc[u][2], acc[u][3]));
#pragma unroll
        for (int o2 = 16; o2; o2 >>= 1) rm = fmaxf(rm, __shfl_xor_sync(0xffffffffu, rm, o2));
        if (tx == 0)
            SMAXPART[((size_t)bh * 512 + rowi) * 8 + blockIdx.x] = rm;
    }
}

// ---------------- K5: single-pass fused attention per (b,i) ----------------
// smem: zs 128*132 (reused as part [8][12][128]) | lg 128*20 | wbT 1536 | smaxs/rinv/redu
__global__ __launch_bounds__(512, 2)
void kattn(const float* __restrict__ z, const float* __restrict__ wb) {
    extern __shared__ float sm[];
    float* zs    = sm;           // 16896 (128 x 132); reused as part (12288) at combine
    float* lg    = sm + 16896;   // 2560 (128 x 20): per-tile exp weights, slots 0..5 / 8..13
    float* wbT   = sm + 19456;   // 1536
    float* smaxs = sm + 20992;   // 16
    float* rinv  = sm + 21008;   // 16
    float* redu  = sm + 21024;   // 48 (total 21072 -> alloc 21088)
    int t = threadIdx.x;
    int l = t & 31, w = t >> 5;
    int jr = w & 3, g = w >> 2;                       // GEMV role: j = jr*32+l, heads {g,g+4,g+8}
    int dc = t & 31, hh = (t >> 5) & 1, js = (t >> 6) & 1, jq = t >> 7;  // agg role
    int row = blockIdx.x, b = row >> 9, i = row & 511;
    const float* zrow = z + (size_t)row * 65536;
    const size_t pl = (size_t)262144;
    const size_t base = (size_t)(b * 12) * pl + (size_t)i * 512;
    int jl = jr * 32 + l;
    // e-store slots in lg row: head h -> slot (h<6 ? h : h+2)
    int s0 = g;                                  // g in 0..3  -> slot g
    int s1 = (g + 4 < 6) ? (g + 4) : (g + 6);    // head g+4
    int s2 = g + 10;                             // head g+8 (>=6)

    for (int e = t; e < 1536; e += 512) {
        int h = e >> 7, c = e & 127;
        wbT[e] = wb[c * 12 + h];
    }
    if (t < 12) {
        const float* sp = SMAXPART + ((size_t)(b * 12 + t) * 512 + i) * 8;
        float m = sp[0];
#pragma unroll
        for (int k = 1; k < 4; k++) m = fmaxf(m, sp[k]);
        smaxs[t] = 0.5773502691896258f * m;
    }

    const float4* w0 = (const float4*)(wbT + g * 128);
    const float4* w1 = (const float4*)(wbT + (g + 4) * 128);
    const float4* w2 = (const float4*)(wbT + (g + 8) * 128);
    float acc[6][4] = {};
    float sh0 = 0.f, sh1 = 0.f, sh2 = 0.f;
    int rbase = jq * 32 + js * 16;

    for (int tile = 0; tile < 4; tile++) {
#pragma unroll
        for (int s = 0; s < 8; s++) {
            int idx = t + s * 512;
            int r = idx >> 5, c4 = idx & 31;
            *(float4*)(zs + r * 132 + c4 * 4) =
                *(const float4*)(zrow + (size_t)(tile * 128 + r) * 128 + c4 * 4);
        }
        __syncthreads();    // zs staged (and wbT/smaxs on first tile)
        // ---- logits + exp for my j = tile*128 + jl (3 heads) ----
        {
            float a0 = 0.f, a1 = 0.f, a2 = 0.f;
            const float4* zv4 = (const float4*)(zs + jl * 132);
#pragma unroll
            for (int c4 = 0; c4 < 32; c4++) {
                float4 zq = zv4[c4];
                float4 x0 = w0[c4], x1 = w1[c4], x2 = w2[c4];
                a0 += zq.x * x0.x + zq.y * x0.y + zq.z * x0.z + zq.w * x0.w;
                a1 += zq.x * x1.x + zq.y * x1.y + zq.z * x1.z + zq.w * x1.w;
                a2 += zq.x * x2.x + zq.y * x2.y + zq.z * x2.z + zq.w * x2.w;
            }
            int j = tile * 128 + jl;
            const float WL = 0.5773502691896258f;
            float e0 = __expf(WL * (a0 + SCA[base + (size_t)g * pl + j])       - smaxs[g]);
            float e1 = __expf(WL * (a1 + SCA[base + (size_t)(g + 4) * pl + j]) - smaxs[g + 4]);
            float e2 = __expf(WL * (a2 + SCA[base + (size_t)(g + 8) * pl + j]) - smaxs[g + 8]);
            SCA[base + (size_t)g * pl + j]       = e0;
            SCA[base + (size_t)(g + 4) * pl + j] = e1;
            SCA[base + (size_t)(g + 8) * pl + j] = e2;
            lg[jl * 20 + s0] = e0;
            lg[jl * 20 + s1] = e1;
            lg[jl * 20 + s2] = e2;
            sh0 += e0; sh1 += e1; sh2 += e2;
        }
        __syncthreads();    // lg ready
        // ---- aggregate: 16 j rows, 6 heads, 4 d per thread ----
#pragma unroll 4
        for (int jj = 0; jj < 16; jj++) {
            int r = rbase + jj;
            float4 zq = *(const float4*)(zs + r * 132 + dc * 4);
            float4 ea = *(const float4*)(lg + r * 20 + hh * 8);
            float2 eb = *(const float2*)(lg + r * 20 + hh * 8 + 4);
            acc[0][0] += ea.x * zq.x; acc[0][1] += ea.x * zq.y; acc[0][2] += ea.x * zq.z; acc[0][3] += ea.x * zq.w;
            acc[1][0] += ea.y * zq.x; acc[1][1] += ea.y * zq.y; acc[1][2] += ea.y * zq.z; acc[1][3] += ea.y * zq.w;
            acc[2][0] += ea.z * zq.x; acc[2][1] += ea.z * zq.y; acc[2][2] += ea.z * zq.z; acc[2][3] += ea.z * zq.w;
            acc[3][0] += ea.w * zq.x; acc[3][1] += ea.w * zq.y; acc[3][2] += ea.w * zq.z; acc[3][3] += ea.w * zq.w;
            acc[4][0] += eb.x * zq.x; acc[4][1] += eb.x * zq.y; acc[4][2] += eb.x * zq.z; acc[4][3] += eb.x * zq.w;
            acc[5][0] += eb.y * zq.x; acc[5][1] += eb.y * zq.y; acc[5][2] += eb.y * zq.z; acc[5][3] += eb.y * zq.w;
        }
        __syncthreads();    // zs/lg reads done before next tile overwrites
    }

    // ---- warp-reduce per-head sums (GEMV roles) ----
#pragma unroll
    for (int o = 16; o; o >>= 1) {
        sh0 += __shfl_xor_sync(0xffffffffu, sh0, o);
        sh1 += __shfl_xor_sync(0xffffffffu, sh1, o);
        sh2 += __shfl_xor_sync(0xffffffffu, sh2, o);
    }
    if (l == 0) { redu[w * 3 + 0] = sh0; redu[w * 3 + 1] = sh1; redu[w * 3 + 2] = sh2; }
    // ---- partials into smem (reuse zs): part[(jq*2+js)][h][128], STS.128 conflict-free ----
    float* part = zs;
#pragma unroll
    for (int k = 0; k < 6; k++) {
        int h = hh * 6 + k;
        *(float4*)(part + (jq * 2 + js) * 1536 + h * 128 + dc * 4) =
            make_float4(acc[k][0], acc[k][1], acc[k][2], acc[k][3]);
    }
    __syncthreads();
    if (t < 12) {
        int h = t, gg = h & 3, k = h >> 2;
        float s = redu[(gg * 4 + 0) * 3 + k] + redu[(gg * 4 + 1) * 3 + k]
                + redu[(gg * 4 + 2) * 3 + k] + redu[(gg * 4 + 3) * 3 + k];
        float r = 1.f / s;
        rinv[h] = r;
        RINVb[(size_t)(b * 12 + h) * 512 + i] = r;
    }
    __syncthreads();
    float* cat = CATb + (size_t)row * 2112;
#pragma unroll
    for (int u = 0; u < 3; u++) {
        int e = t + u * 512;
        int h = e >> 7, d = e & 127;
        float s = 0.f;
#pragma unroll
        for (int grp = 0; grp < 8; grp++)
            s += part[grp * 1536 + h * 128 + d];
        cat[h * 128 + d] = s * rinv[h];
    }
}

// ---------------- K6: value aggregation GEMMs  E[bh] x [v|tv], normalize by rinv ----------------
// Thread owns row il and 10 CONSECUTIVE cols cp*10..cp*10+9 -> Bs read as 5x LDS.64
__global__ __launch_bounds__(256) void kagg() {
    __shared__ float As[64 * 68];   // [i][j], pitch 68
    __shared__ float Bs[64 * 42];   // [j][c], even pitch for float2 reads
    int t = threadIdx.x;
    int bh = blockIdx.y, b = bh / 12, h = bh % 12;
    int i0 = blockIdx.x * 64;
    int il = t & 63, cp = t >> 6;
    float acc[10] = {};
    for (int jt = 0; jt < 8; jt++) {
        __syncthreads();
#pragma unroll
        for (int s = 0; s < 4; s++) {
            int idx = t + s * 256;
            int r = idx >> 4, j4 = (idx & 15) * 4;
            float4 v = *(const float4*)(SCA + ((size_t)bh * 512 + i0 + r) * 512 + jt * 64 + j4);
            *(float4*)(As + r * 68 + j4) = v;
        }
#pragma unroll
        for (int s = 0; s < 10; s++) {
            int idx = t + s * 256;
            int jj = idx / 40, c = idx - jj * 40;
            Bs[jj * 42 + c] = VTb[(size_t)(b * 512 + jt * 64 + jj) * 480 + h * 40 + c];
        }
        __syncthreads();
        const float4* a4 = (const float4*)(As + il * 68);
#pragma unroll
        for (int j4 = 0; j4 < 16; j4++) {
            float4 av = a4[j4];
#pragma unroll
            for (int u = 0; u < 4; u++) {
                float a = u == 0 ? av.x : u == 1 ? av.y : u == 2 ? av.z : av.w;
                const float2* b2 = (const float2*)(Bs + (j4 * 4 + u) * 42 + cp * 10);
#pragma unroll
                for (int k = 0; k < 5; k++) {
                    float2 bv = b2[k];
                    acc[2 * k]     += a * bv.x;
                    acc[2 * k + 1] += a * bv.y;
                }
            }
        }
    }
    float rv = RINVb[(size_t)bh * 512 + i0 + il];
    size_t crow = (size_t)(b * 512 + i0 + il);
#pragma unroll
    for (int cc = 0; cc < 10; cc++) {
        int col = cp * 10 + cc;
        float v = acc[cc] * rv;
        if (col < 16) CATb[crow * 2112 + 1536 + h * 16 + col] = v;
        else          OHP[crow * 288 + h * 24 + (col - 16)] = v;
    }
}

// ---------------- K7: rigid invert + norms ----------------
__global__ void kepi(const float* __restrict__ rots, const float* __restrict__ trans) {
    __shared__ float R[9], T[3];
    int row = blockIdx.x, t = threadIdx.x;   // 96 threads
    if (t < 9) R[t] = rots[row * 9 + t];
    if (t < 3) T[t] = trans[row * 3 + t];
    __syncthreads();
    size_t base = (size_t)row * 288 + t * 3;
    float gx = OHP[base + 0] - T[0];
    float gy = OHP[base + 1] - T[1];
    float gz = OHP[base + 2] - T[2];
    float lx = R[0] * gx + R[3] * gy + R[6] * gz;
    float ly = R[1] * gx + R[4] * gy + R[7] * gz;
    float lz = R[2] * gx + R[5] * gy + R[8] * gz;
    float* cat = CATb + (size_t)row * 2112;
    cat[1728 + t * 3 + 0] = lx;
    cat[1728 + t * 3 + 1] = ly;
    cat[1728 + t * 3 + 2] = lz;
    cat[2016 + t] = sqrtf(lx * lx + ly * ly + lz * lz);
}

extern "C" void kernel_launch(void* const* d_in, const int* in_sizes, int n_in,
                              void* d_out, int out_size) {
    const float* s_i   = (const float*)d_in[0];
    const float* z_ij  = (const float*)d_in[1];
    const float* rots  = (const float*)d_in[2];
    const float* trans = (const float*)d_in[3];
    const float* wq    = (const float*)d_in[4];
    const float* wk    = (const float*)d_in[5];
    const float* wv    = (const float*)d_in[6];
    const float* wqp   = (const float*)d_in[7];
    const float* wkp   = (const float*)d_in[8];
    const float* wvp   = (const float*)d_in[9];
    const float* wb    = (const float*)d_in[10];
    const float* gamma = (const float*)d_in[11];
    const float* wout  = (const float*)d_in[12];
    const float* bout  = (const float*)d_in[13];
    float* out = (float*)d_out;

    float* dWPROJ; cudaGetSymbolAddress((void**)&dWPROJ, WPROJ);
    float* dPROJ;  cudaGetSymbolAddress((void**)&dPROJ, PROJ);
    float* dCAT;   cudaGetSymbolAddress((void**)&dCAT, CATb);
    float* dOUTP;  cudaGetSymbolAddress((void**)&dOUTP, OUTPART);

    static int smem_set = 0;
    const int KATTN_SMEM = 21088 * 4;
    if (!smem_set) {
        cudaFuncSetAttribute(kattn, cudaFuncAttributeMaxDynamicSharedMemorySize, KATTN_SMEM);
        smem_set = 1;
    }

    kpack<<<1728, 256>>>(wq, wk, wv, wqp, wkp, wvp);
    {   // PROJ = s_i @ WPROJ : 1024 x 1152 x 384  (64x64 tiles -> 18x16 = 288 CTAs)
        dim3 g(1152 / 64, 1024 / 64, 1);
        sgemm_k<<<g, 256>>>(s_i, dWPROJ, dPROJ, 1024, 1152, 384, 384, nullptr);
    }
    ktransform<<<1024, 32>>>(rots, trans, gamma);
    {   // kscore: 64i x 128j tiles -> 4 x 8 x 24 = 768 CTAs
        dim3 g(4, 8, 24);
        kscore<<<g, 256>>>();
    }
    kattn<<<1024, 512, KATTN_SMEM>>>(z_ij, wb);
    {
        dim3 g(8, 24);
        kagg<<<g, 256>>>();
    }
    kepi<<<1024, 96>>>(rots, trans);
    {   // OUTPART[s] = CAT @ wout over K-slice s : 1024 x 384 x (4 x 528) -> 6x16x4 = 384 CTAs
        dim3 g(384 / 64, 1024 / 64, 4);
        sgemm_k<<<g, 256>>>(dCAT, wout, dOUTP, 1024, 384, 2112, 528, nullptr);
    }
    kreduce<<<384, 256>>>(out, bout);
}

// round 17
// speedup vs baseline: 1.0207x; 1.0207x over previous
#include <cuda_runtime.h>
#include <math.h>

// B=2 N=512 CS=384 CZ=128 H=12 D=16 P=4 PV=8
// PROJ cols: q 0..191 | k 192..383 | v 384..575 | qp 576..719 | kp 720..863 | vp 864..1151
// CAT=2112: o_hat 0..1535 | o 1536..1727 | o_hp 1728..2015 | norm 2016..2111

__device__ float WPROJ[384 * 1152];
__device__ float PROJ[1024 * 1152];
__device__ float QQb[1024 * 384];
__device__ float KKb[1024 * 384];
__device__ float VTb[1024 * 480];           // per key row: 12h x [v(16) | tv(24)]
__device__ float CATb[1024 * 2112];
__device__ float SCA[2 * 12 * 512 * 512];   // scores, then unnormalized exp weights (in-place)
__device__ float SMAXPART[24 * 512 * 8];    // per (b,h,i): block maxes over 4 j-blocks (slots 0..3)
__device__ float RINVb[24 * 512];           // per (b,h,i): 1/sum(exp)
__device__ float OUTPART[4 * 1024 * 384];   // split-K partials for output GEMM

// ---------------- K1: pack projection weights ----------------
__global__ void kpack(const float* __restrict__ wq, const float* __restrict__ wk,
                      const float* __restrict__ wv, const float* __restrict__ wqp,
                      const float* __restrict__ wkp, const float* __restrict__ wvp) {
    int e = blockIdx.x * 256 + threadIdx.x;  // 1728*256 = 442368 = 384*1152
    int c = e / 1152, col = e - c * 1152;
    float v;
    if (col < 192)       v = wq[c * 192 + col];
    else if (col < 384)  v = wk[c * 192 + col - 192];
    else if (col < 576)  v = wv[c * 192 + col - 384];
    else if (col < 720)  v = wqp[c * 144 + col - 576];
    else if (col < 864)  v = wkp[c * 144 + col - 720];
    else                 v = wvp[c * 288 + col - 864];
    WPROJ[e] = v;
}

// ---------------- tiled SGEMM 64x64x16, double-buffered, optional split-K ----------------
__global__ __launch_bounds__(256)
void sgemm_k(const float* __restrict__ A, const float* __restrict__ Bm,
             float* __restrict__ C, int M, int Nn, int K, int Ksl,
             const float* __restrict__ bias) {
    __shared__ float As[2][16][64];
    __shared__ float Bs[2][16][64];
    int t = threadIdx.x;
    int tx = t % 16, ty = t / 16;
    int row0 = blockIdx.y * 64, col0 = blockIdx.x * 64;
    int kbeg = blockIdx.z * Ksl;
    float* Cp = C + (size_t)blockIdx.z * M * Nn;
    int ar = t >> 2, akk = (t & 3) * 4;     // A stage: row, k4
    int bkk = t >> 4, bn4 = (t & 15) * 4;   // B stage: k, n4
    float acc[4][4] = {};
    {   // preload stage 0
        float4 va = *(const float4*)(A + (size_t)(row0 + ar) * K + kbeg + akk);
        As[0][akk][ar] = va.x; As[0][akk + 1][ar] = va.y;
        As[0][akk + 2][ar] = va.z; As[0][akk + 3][ar] = va.w;
        *(float4*)(&Bs[0][bkk][bn4]) =
            *(const float4*)(Bm + (size_t)(kbeg + bkk) * Nn + col0 + bn4);
    }
    __syncthreads();
    int nst = Ksl / 16;
    for (int s = 0; s < nst; s++) {
        int cur = s & 1, nxt = cur ^ 1;
        float4 va, vb;
        bool more = (s + 1 < nst);
        if (more) {   // issue next-tile LDGs before compute (latency hidden)
            int k0 = kbeg + (s + 1) * 16;
            va = *(const float4*)(A + (size_t)(row0 + ar) * K + k0 + akk);
            vb = *(const float4*)(Bm + (size_t)(k0 + bkk) * Nn + col0 + bn4);
        }
#pragma unroll
        for (int kk = 0; kk < 16; kk++) {
            float4 ra = *(const float4*)(&As[cur][kk][ty * 4]);
            float4 rb = *(const float4*)(&Bs[cur][kk][tx * 4]);
            acc[0][0] += ra.x * rb.x; acc[0][1] += ra.x * rb.y; acc[0][2] += ra.x * rb.z; acc[0][3] += ra.x * rb.w;
            acc[1][0] += ra.y * rb.x; acc[1][1] += ra.y * rb.y; acc[1][2] += ra.y * rb.z; acc[1][3] += ra.y * rb.w;
            acc[2][0] += ra.z * rb.x; acc[2][1] += ra.z * rb.y; acc[2][2] += ra.z * rb.z; acc[2][3] += ra.z * rb.w;
            acc[3][0] += ra.w * rb.x; acc[3][1] += ra.w * rb.y; acc[3][2] += ra.w * rb.z; acc[3][3] += ra.w * rb.w;
        }
        if (more) {
            As[nxt][akk][ar] = va.x; As[nxt][akk + 1][ar] = va.y;
            As[nxt][akk + 2][ar] = va.z; As[nxt][akk + 3][ar] = va.w;
            *(float4*)(&Bs[nxt][bkk][bn4]) = vb;
            __syncthreads();
        }
    }
#pragma unroll
    for (int u = 0; u < 4; u++) {
        int r = row0 + ty * 4 + u;
        float4 o = make_float4(acc[u][0], acc[u][1], acc[u][2], acc[u][3]);
        if (bias) {
            const float4 bb = *(const float4*)(bias + col0 + tx * 4);
            o.x += bb.x; o.y += bb.y; o.z += bb.z; o.w += bb.w;
        }
        *(float4*)(Cp + (size_t)r * Nn + col0 + tx * 4) = o;
    }
}

// ---------------- reduce split-K partials + bias (float4) ----------------
__global__ void kreduce(float* __restrict__ out, const float* __restrict__ bout) {
    int e = (blockIdx.x * 256 + threadIdx.x) * 4;   // 98304 threads x 4 = 393216
    const int PL = 1024 * 384;
    float4 a = *(const float4*)(OUTPART + e);
    float4 b = *(const float4*)(OUTPART + PL + e);
    float4 c = *(const float4*)(OUTPART + 2 * PL + e);
    float4 d = *(const float4*)(OUTPART + 3 * PL + e);
    float4 bb = *(const float4*)(bout + (e % 384));
    float4 o;
    o.x = a.x + b.x + c.x + d.x + bb.x;
    o.y = a.y + b.y + c.y + d.y + bb.y;
    o.z = a.z + b.z + c.z + d.z + bb.z;
    o.w = a.w + b.w + c.w + d.w + bb.w;
    *(float4*)(out + e) = o;
}

// ---------------- K3: rigid transforms + QQ/KK/VT packing (8 rows per CTA) ----------------
__global__ __launch_bounds__(96) void ktransform(const float* __restrict__ rots,
                                                 const float* __restrict__ trans,
                                                 const float* __restrict__ gamma) {
    int row = blockIdx.x * 8 + threadIdx.x / 12;
    int h = threadIdx.x % 12;
    const float* pr = PROJ + (size_t)row * 1152;
    float R0 = rots[row * 9 + 0], R1 = rots[row * 9 + 1], R2 = rots[row * 9 + 2];
    float R3 = rots[row * 9 + 3], R4 = rots[row * 9 + 4], R5 = rots[row * 9 + 5];
    float R6 = rots[row * 9 + 6], R7 = rots[row * 9 + 7], R8 = rots[row * 9 + 8];
    float t0 = trans[row * 3 + 0], t1 = trans[row * 3 + 1], t2 = trans[row * 3 + 2];
    float* QQ = QQb + (size_t)row * 384 + h * 32;
    float* KK = KKb + (size_t)row * 384 + h * 32;
    float cg = 0.11785113019775793f * gamma[h];  // 0.5 * sqrt(2/36) * gamma
#pragma unroll
    for (int d = 0; d < 16; d++) {
        QQ[d] = pr[h * 16 + d] * 0.25f;          // fold 1/sqrt(D)
        KK[d] = pr[192 + h * 16 + d];
    }
    float sq2 = 0.f, sk2 = 0.f;
#pragma unroll
    for (int p = 0; p < 4; p++) {
        const float* qp = pr + 576 + h * 12 + p * 3;
        float x = qp[0], y = qp[1], zz = qp[2];
        float gx = R0 * x + R1 * y + R2 * zz + t0;
        float gy = R3 * x + R4 * y + R5 * zz + t1;
        float gz = R6 * x + R7 * y + R8 * zz + t2;
        QQ[16 + p * 3 + 0] = 2.f * cg * gx;
        QQ[16 + p * 3 + 1] = 2.f * cg * gy;
        QQ[16 + p * 3 + 2] = 2.f * cg * gz;
        sq2 += gx * gx + gy * gy + gz * gz;
        const float* kp = pr + 720 + h * 12 + p * 3;
        x = kp[0]; y = kp[1]; zz = kp[2];
        gx = R0 * x + R1 * y + R2 * zz + t0;
        gy = R3 * x + R4 * y + R5 * zz + t1;
        gz = R6 * x + R7 * y + R8 * zz + t2;
        KK[16 + p * 3 + 0] = gx; KK[16 + p * 3 + 1] = gy; KK[16 + p * 3 + 2] = gz;
        sk2 += gx * gx + gy * gy + gz * gz;
    }
    QQ[28] = -cg;       KK[28] = sk2;
    QQ[29] = -cg * sq2; KK[29] = 1.f;
    QQ[30] = 0.f; QQ[31] = 0.f; KK[30] = 0.f; KK[31] = 0.f;
    // pack [v | tv] for kagg
    float* vt = VTb + (size_t)row * 480 + h * 40;
#pragma unroll
    for (int d = 0; d < 16; d++) vt[d] = pr[384 + h * 16 + d];
#pragma unroll
    for (int p = 0; p < 8; p++) {
        const float* vp = pr + 864 + h * 24 + p * 3;
        float x = vp[0], y = vp[1], zz = vp[2];
        vt[16 + p * 3 + 0] = R0 * x + R1 * y + R2 * zz + t0;
        vt[16 + p * 3 + 1] = R3 * x + R4 * y + R5 * zz + t1;
        vt[16 + p * 3 + 2] = R6 * x + R7 * y + R8 * zz + t2;
    }
}

// ---------------- K4: score GEMM 64i x 128j + per-row block maxes ----------------
__global__ __launch_bounds__(256) void kscore() {
    __shared__ float As[32][68];    // QQ: [c][i], 64 i
    __shared__ float Bs[32][132];   // KK: [c][j], 128 j
    int t = threadIdx.x;
    int bh = blockIdx.z, b = bh / 12, h = bh % 12;
    int i0 = blockIdx.y * 64, j0 = blockIdx.x * 128;
#pragma unroll
    for (int s = 0; s < 2; s++) {
        int idx = t + s * 256;
        int r = idx >> 3, c4 = (idx & 7) * 4;
        float4 va = *(const float4*)(QQb + (size_t)(b * 512 + i0 + r) * 384 + h * 32 + c4);
        As[c4][r] = va.x; As[c4 + 1][r] = va.y; As[c4 + 2][r] = va.z; As[c4 + 3][r] = va.w;
    }
#pragma unroll
    for (int s = 0; s < 4; s++) {
        int idx = t + s * 256;
        int r = idx >> 3, c4 = (idx & 7) * 4;
        float4 vb = *(const float4*)(KKb + (size_t)(b * 512 + j0 + r) * 384 + h * 32 + c4);
        Bs[c4][r] = vb.x; Bs[c4 + 1][r] = vb.y; Bs[c4 + 2][r] = vb.z; Bs[c4 + 3][r] = vb.w;
    }
    __syncthreads();
    int tx = t & 31, ty = t >> 5;   // tx: 32 x 4j = 128, ty: 8 x 8i = 64
    float acc[8][4] = {};
#pragma unroll
    for (int kk = 0; kk < 32; kk++) {
        float4 a0 = *(const float4*)(&As[kk][ty * 8]);
        float4 a1 = *(const float4*)(&As[kk][ty * 8 + 4]);
        float4 rb = *(const float4*)(&Bs[kk][tx * 4]);
        acc[0][0] += a0.x * rb.x; acc[0][1] += a0.x * rb.y; acc[0][2] += a0.x * rb.z; acc[0][3] += a0.x * rb.w;
        acc[1][0] += a0.y * rb.x; acc[1][1] += a0.y * rb.y; acc[1][2] += a0.y * rb.z; acc[1][3] += a0.y * rb.w;
        acc[2][0] += a0.z * rb.x; acc[2][1] += a0.z * rb.y; acc[2][2] += a0.z * rb.z; acc[2][3] += a0.z * rb.w;
        acc[3][0] += a0.w * rb.x; acc[3][1] += a0.w * rb.y; acc[3][2] += a0.w * rb.z; acc[3][3] += a0.w * rb.w;
        acc[4][0] += a1.x * rb.x; acc[4][1] += a1.x * rb.y; acc[4][2] += a1.x * rb.z; acc[4][3] += a1.x * rb.w;
        acc[5][0] += a1.y * rb.x; acc[5][1] += a1.y * rb.y; acc[5][2] += a1.y * rb.z; acc[5][3] += a1.y * rb.w;
        acc[6][0] += a1.z * rb.x; acc[6][1] += a1.z * rb.y; acc[6][2] += a1.z * rb.z; acc[6][3] += a1.z * rb.w;
        acc[7][0] += a1.w * rb.x; acc[7][1] += a1.w * rb.y; acc[7][2] += a1.w * rb.z; acc[7][3] += a1.w * rb.w;
    }
#pragma unroll
    for (int u = 0; u < 8; u++) {
        int rowi = i0 + ty * 8 + u;
        float4 o = make_float4(acc[u][0], acc[u][1], acc[u][2], acc[u][3]);
        *(float4*)(SCA + ((size_t)bh * 512 + rowi) * 512 + j0 + tx * 4) = o;
        float rm = fmaxf(fmaxf(acc[u][0], acc[u][1]), fmaxf(acc[u][2], acc[u][3]));
#pragma unroll
        for (int o2 = 16; o2; o2 >>= 1) rm = fmaxf(rm, __shfl_xor_sync(0xffffffffu, rm, o2));
        if (tx == 0)
            SMAXPART[((size_t)bh * 512 + rowi) * 8 + blockIdx.x] = rm;
    }
}

// ---------------- K5: single-pass fused attention per (b,i) ----------------
// smem: zs 128*132 (reused as part [8][12][128]) | lg 128*20 | wbT 1536 | smaxs/rinv/redu
__global__ __launch_bounds__(512, 2)
void kattn(const float* __restrict__ z, const float* __restrict__ wb) {
    extern __shared__ float sm[];
    float* zs    = sm;           // 16896 (128 x 132); reused as part (12288) at combine
    float* lg    = sm + 16896;   // 2560 (128 x 20): per-tile exp weights, slots 0..5 / 8..13
    float* wbT   = sm + 19456;   // 1536
    float* smaxs = sm + 20992;   // 16
    float* rinv  = sm + 21008;   // 16
    float* redu  = sm + 21024;   // 48 (total 21072 -> alloc 21088)
    int t = threadIdx.x;
    int l = t & 31, w = t >> 5;
    int jr = w & 3, g = w >> 2;                       // GEMV role: j = jr*32+l, heads {g,g+4,g+8}
    int dc = t & 31, hh = (t >> 5) & 1, js = (t >> 6) & 1, jq = t >> 7;  // agg role
    int row = blockIdx.x, b = row >> 9, i = row & 511;
    const float* zrow = z + (size_t)row * 65536;
    const size_t pl = (size_t)262144;
    const size_t base = (size_t)(b * 12) * pl + (size_t)i * 512;
    int jl = jr * 32 + l;
    // e-store slots in lg row: head h -> slot (h<6 ? h : h+2)
    int s0 = g;                                  // g in 0..3  -> slot g
    int s1 = (g + 4 < 6) ? (g + 4) : (g + 6);    // head g+4
    int s2 = g + 10;                             // head g+8 (>=6)

    for (int e = t; e < 1536; e += 512) {
        int h = e >> 7, c = e & 127;
        wbT[e] = wb[c * 12 + h];
    }
    if (t < 12) {
        const float* sp = SMAXPART + ((size_t)(b * 12 + t) * 512 + i) * 8;
        float m = sp[0];
#pragma unroll
        for (int k = 1; k < 4; k++) m = fmaxf(m, sp[k]);
        smaxs[t] = 0.5773502691896258f * m;
    }

    const float4* w0 = (const float4*)(wbT + g * 128);
    const float4* w1 = (const float4*)(wbT + (g + 4) * 128);
    const float4* w2 = (const float4*)(wbT + (g + 8) * 128);
    float acc[6][4] = {};
    float sh0 = 0.f, sh1 = 0.f, sh2 = 0.f;
    int rbase = jq * 32 + js * 16;

    for (int tile = 0; tile < 4; tile++) {
#pragma unroll
        for (int s = 0; s < 8; s++) {
            int idx = t + s * 512;
            int r = idx >> 5, c4 = idx & 31;
            *(float4*)(zs + r * 132 + c4 * 4) =
                *(const float4*)(zrow + (size_t)(tile * 128 + r) * 128 + c4 * 4);
        }
        __syncthreads();    // zs staged (and wbT/smaxs on first tile)
        // ---- logits + exp for my j = tile*128 + jl (3 heads) ----
        {
            float a0 = 0.f, a1 = 0.f, a2 = 0.f;
            const float4* zv4 = (const float4*)(zs + jl * 132);
#pragma unroll
            for (int c4 = 0; c4 < 32; c4++) {
                float4 zq = zv4[c4];
                float4 x0 = w0[c4], x1 = w1[c4], x2 = w2[c4];
                a0 += zq.x * x0.x + zq.y * x0.y + zq.z * x0.z + zq.w * x0.w;
                a1 += zq.x * x1.x + zq.y * x1.y + zq.z * x1.z + zq.w * x1.w;
                a2 += zq.x * x2.x + zq.y * x2.y + zq.z * x2.z + zq.w * x2.w;
            }
            int j = tile * 128 + jl;
            const float WL = 0.5773502691896258f;
            float e0 = __expf(WL * (a0 + SCA[base + (size_t)g * pl + j])       - smaxs[g]);
            float e1 = __expf(WL * (a1 + SCA[base + (size_t)(g + 4) * pl + j]) - smaxs[g + 4]);
            float e2 = __expf(WL * (a2 + SCA[base + (size_t)(g + 8) * pl + j]) - smaxs[g + 8]);
            SCA[base + (size_t)g * pl + j]       = e0;
            SCA[base + (size_t)(g + 4) * pl + j] = e1;
            SCA[base + (size_t)(g + 8) * pl + j] = e2;
            lg[jl * 20 + s0] = e0;
            lg[jl * 20 + s1] = e1;
            lg[jl * 20 + s2] = e2;
            sh0 += e0; sh1 += e1; sh2 += e2;
        }
        __syncthreads();    // lg ready
        // ---- aggregate: 16 j rows, 6 heads, 4 d per thread ----
#pragma unroll 4
        for (int jj = 0; jj < 16; jj++) {
            int r = rbase + jj;
            float4 zq = *(const float4*)(zs + r * 132 + dc * 4);
            float4 ea = *(const float4*)(lg + r * 20 + hh * 8);
            float2 eb = *(const float2*)(lg + r * 20 + hh * 8 + 4);
            acc[0][0] += ea.x * zq.x; acc[0][1] += ea.x * zq.y; acc[0][2] += ea.x * zq.z; acc[0][3] += ea.x * zq.w;
            acc[1][0] += ea.y * zq.x; acc[1][1] += ea.y * zq.y; acc[1][2] += ea.y * zq.z; acc[1][3] += ea.y * zq.w;
            acc[2][0] += ea.z * zq.x; acc[2][1] += ea.z * zq.y; acc[2][2] += ea.z * zq.z; acc[2][3] += ea.z * zq.w;
            acc[3][0] += ea.w * zq.x; acc[3][1] += ea.w * zq.y; acc[3][2] += ea.w * zq.z; acc[3][3] += ea.w * zq.w;
            acc[4][0] += eb.x * zq.x; acc[4][1] += eb.x * zq.y; acc[4][2] += eb.x * zq.z; acc[4][3] += eb.x * zq.w;
            acc[5][0] += eb.y * zq.x; acc[5][1] += eb.y * zq.y; acc[5][2] += eb.y * zq.z; acc[5][3] += eb.y * zq.w;
        }
        __syncthreads();    // zs/lg reads done before next tile overwrites
    }

    // ---- warp-reduce per-head sums (GEMV roles) ----
#pragma unroll
    for (int o = 16; o; o >>= 1) {
        sh0 += __shfl_xor_sync(0xffffffffu, sh0, o);
        sh1 += __shfl_xor_sync(0xffffffffu, sh1, o);
        sh2 += __shfl_xor_sync(0xffffffffu, sh2, o);
    }
    if (l == 0) { redu[w * 3 + 0] = sh0; redu[w * 3 + 1] = sh1; redu[w * 3 + 2] = sh2; }
    // ---- partials into smem (reuse zs): part[(jq*2+js)][h][128], STS.128 conflict-free ----
    float* part = zs;
#pragma unroll
    for (int k = 0; k < 6; k++) {
        int h = hh * 6 + k;
        *(float4*)(part + (jq * 2 + js) * 1536 + h * 128 + dc * 4) =
            make_float4(acc[k][0], acc[k][1], acc[k][2], acc[k][3]);
    }
    __syncthreads();
    if (t < 12) {
        int h = t, gg = h & 3, k = h >> 2;
        float s = redu[(gg * 4 + 0) * 3 + k] + redu[(gg * 4 + 1) * 3 + k]
                + redu[(gg * 4 + 2) * 3 + k] + redu[(gg * 4 + 3) * 3 + k];
        float r = 1.f / s;
        rinv[h] = r;
        RINVb[(size_t)(b * 12 + h) * 512 + i] = r;
    }
    __syncthreads();
    float* cat = CATb + (size_t)row * 2112;
#pragma unroll
    for (int u = 0; u < 3; u++) {
        int e = t + u * 512;
        int h = e >> 7, d = e & 127;
        float s = 0.f;
#pragma unroll
        for (int grp = 0; grp < 8; grp++)
            s += part[grp * 1536 + h * 128 + d];
        cat[h * 128 + d] = s * rinv[h];
    }
}

// ---------------- K6: value aggregation GEMM + fused rigid-invert epilogue ----------------
// Thread owns row il and 10 CONSECUTIVE cols cp*10..cp*10+9 -> Bs read as 5x LDS.64
__global__ __launch_bounds__(256) void kagg(const float* __restrict__ rots,
                                            const float* __restrict__ trans) {
    __shared__ float As[64 * 68];   // [i][j], pitch 68
    __shared__ float Bs[64 * 42];   // [j][c]; later reused as gl-frame points [64][24]
    int t = threadIdx.x;
    int bh = blockIdx.y, b = bh / 12, h = bh % 12;
    int i0 = blockIdx.x * 64;
    int il = t & 63, cp = t >> 6;
    float acc[10] = {};
    for (int jt = 0; jt < 8; jt++) {
        __syncthreads();
#pragma unroll
        for (int s = 0; s < 4; s++) {
            int idx = t + s * 256;
            int r = idx >> 4, j4 = (idx & 15) * 4;
            float4 v = *(const float4*)(SCA + ((size_t)bh * 512 + i0 + r) * 512 + jt * 64 + j4);
            *(float4*)(As + r * 68 + j4) = v;
        }
#pragma unroll
        for (int s = 0; s < 10; s++) {
            int idx = t + s * 256;
            int jj = idx / 40, c = idx - jj * 40;
            Bs[jj * 42 + c] = VTb[(size_t)(b * 512 + jt * 64 + jj) * 480 + h * 40 + c];
        }
        __syncthreads();
        const float4* a4 = (const float4*)(As + il * 68);
#pragma unroll
        for (int j4 = 0; j4 < 16; j4++) {
            float4 av = a4[j4];
#pragma unroll
            for (int u = 0; u < 4; u++) {
                float a = u == 0 ? av.x : u == 1 ? av.y : u == 2 ? av.z : av.w;
                const float2* b2 = (const float2*)(Bs + (j4 * 4 + u) * 42 + cp * 10);
#pragma unroll
                for (int k = 0; k < 5; k++) {
                    float2 bv = b2[k];
                    acc[2 * k]     += a * bv.x;
                    acc[2 * k + 1] += a * bv.y;
                }
            }
        }
    }
    float rv = RINVb[(size_t)bh * 512 + i0 + il];
    size_t crow = (size_t)(b * 512 + i0 + il);
    __syncthreads();   // all Bs reads done -> reuse as gl-frame point buffer [il][24]
#pragma unroll
    for (int cc = 0; cc < 10; cc++) {
        int col = cp * 10 + cc;
        float v = acc[cc] * rv;
        if (col < 16) CATb[crow * 2112 + 1536 + h * 16 + col] = v;
        else          Bs[il * 24 + (col - 16)] = v;
    }
    __syncthreads();
    // ---- epilogue: 512 point tasks (64 rows x 8 points), 2 per thread ----
#pragma unroll
    for (int s = 0; s < 2; s++) {
        int task = s * 256 + t;
        int rl = task >> 3, p = task & 7;
        int grow = b * 512 + i0 + rl;
        float gx = Bs[rl * 24 + p * 3 + 0] - trans[grow * 3 + 0];
        float gy = Bs[rl * 24 + p * 3 + 1] - trans[grow * 3 + 1];
        float gz = Bs[rl * 24 + p * 3 + 2] - trans[grow * 3 + 2];
        const float* R = rots + grow * 9;
        float lx = R[0] * gx + R[3] * gy + R[6] * gz;
        float ly = R[1] * gx + R[4] * gy + R[7] * gz;
        float lz = R[2] * gx + R[5] * gy + R[8] * gz;
        float* cat = CATb + (size_t)grow * 2112;
        int e = h * 8 + p;
        cat[1728 + e * 3 + 0] = lx;
        cat[1728 + e * 3 + 1] = ly;
        cat[1728 + e * 3 + 2] = lz;
        cat[2016 + e] = sqrtf(lx * lx + ly * ly + lz * lz);
    }
}

extern "C" void kernel_launch(void* const* d_in, const int* in_sizes, int n_in,
                              void* d_out, int out_size) {
    const float* s_i   = (const float*)d_in[0];
    const float* z_ij  = (const float*)d_in[1];
    const float* rots  = (const float*)d_in[2];
    const float* trans = (const float*)d_in[3];
    const float* wq    = (const float*)d_in[4];
    const float* wk    = (const float*)d_in[5];
    const float* wv    = (const float*)d_in[6];
    const float* wqp   = (const float*)d_in[7];
    const float* wkp   = (const float*)d_in[8];
    const float* wvp   = (const float*)d_in[9];
    const float* wb    = (const float*)d_in[10];
    const float* gamma = (const float*)d_in[11];
    const float* wout  = (const float*)d_in[12];
    const float* bout  = (const float*)d_in[13];
    float* out = (float*)d_out;

    float* dWPROJ; cudaGetSymbolAddress((void**)&dWPROJ, WPROJ);
    float* dPROJ;  cudaGetSymbolAddress((void**)&dPROJ, PROJ);
    float* dCAT;   cudaGetSymbolAddress((void**)&dCAT, CATb);
    float* dOUTP;  cudaGetSymbolAddress((void**)&dOUTP, OUTPART);

    static int smem_set = 0;
    const int KATTN_SMEM = 21088 * 4;
    if (!smem_set) {
        cudaFuncSetAttribute(kattn, cudaFuncAttributeMaxDynamicSharedMemorySize, KATTN_SMEM);
        smem_set = 1;
    }

    kpack<<<1728, 256>>>(wq, wk, wv, wqp, wkp, wvp);
    {   // PROJ = s_i @ WPROJ : 1024 x 1152 x 384  (64x64 tiles -> 18x16 = 288 CTAs)
        dim3 g(1152 / 64, 1024 / 64, 1);
        sgemm_k<<<g, 256>>>(s_i, dWPROJ, dPROJ, 1024, 1152, 384, 384, nullptr);
    }
    ktransform<<<128, 96>>>(rots, trans, gamma);
    {   // kscore: 64i x 128j tiles -> 4 x 8 x 24 = 768 CTAs
        dim3 g(4, 8, 24);
        kscore<<<g, 256>>>();
    }
    kattn<<<1024, 512, KATTN_SMEM>>>(z_ij, wb);
    {
        dim3 g(8, 24);
        kagg<<<g, 256>>>(rots, trans);
    }
    {   // OUTPART[s] = CAT @ wout over K-slice s : 1024 x 384 x (4 x 528) -> 6x16x4 = 384 CTAs
        dim3 g(384 / 64, 1024 / 64, 4);
        sgemm_k<<<g, 256>>>(dCAT, wout, dOUTP, 1024, 384, 2112, 528, nullptr);
    }
    kreduce<<<384, 256>>>(out, bout);
}